// round 4
// baseline (speedup 1.0000x reference)
#include <cuda_runtime.h>
#include <cuda_bf16.h>
#include <cstdint>

#define B_ROWS  32768
#define D_DIM   256
#define K_CODES 2048

// output layout (float32): quantized_st[B*D], vq_loss, entropy, inds[B], cluster_metric
#define OFF_VQ  8388608
#define OFF_ENT 8388609
#define OFF_IND 8388610
#define OFF_CL  8421378

#define TIE_EPS 1e-4f

// ---------------- device scratch ----------------
__device__ __nv_bfloat16 g_ah[B_ROWS * D_DIM];
__device__ __nv_bfloat16 g_al[B_ROWS * D_DIM];
__device__ __nv_bfloat16 g_eh[K_CODES * D_DIM];
__device__ __nv_bfloat16 g_el[K_CODES * D_DIM];
__device__ float g_xsq[B_ROWS];
__device__ float g_esq[K_CODES];
__device__ int   g_ind[B_ROWS];
__device__ int   g_flag[B_ROWS];
__device__ float g_cl_val[B_ROWS];
__device__ int   g_counts[K_CODES];
__device__ float g_mse_part[8192];

// ---------------- PTX helpers (base sm_103 only — NO tcgen05) ----------------
__device__ __forceinline__ uint32_t smem_to_u32(const void* p) {
    uint32_t a;
    asm("{ .reg .u64 t; cvta.to.shared.u64 t, %1; cvt.u32.u64 %0, t; }"
        : "=r"(a) : "l"(p));
    return a;
}
__device__ __forceinline__ void ldm4(uint32_t* d, uint32_t addr) {
    asm volatile("ldmatrix.sync.aligned.m8n8.x4.shared.b16 {%0,%1,%2,%3}, [%4];"
        : "=r"(d[0]), "=r"(d[1]), "=r"(d[2]), "=r"(d[3]) : "r"(addr));
}
__device__ __forceinline__ void mma_bf16(float* c, const uint32_t* a,
                                         uint32_t b0, uint32_t b1) {
    asm volatile("mma.sync.aligned.m16n8k16.row.col.f32.bf16.bf16.f32 "
        "{%0,%1,%2,%3}, {%4,%5,%6,%7}, {%8,%9}, {%0,%1,%2,%3};"
        : "+f"(c[0]), "+f"(c[1]), "+f"(c[2]), "+f"(c[3])
        : "r"(a[0]), "r"(a[1]), "r"(a[2]), "r"(a[3]), "r"(b0), "r"(b1));
}
__device__ __forceinline__ void cpa16(uint32_t dst, const void* src) {
    asm volatile("cp.async.cg.shared.global [%0], [%1], 16;"
        :: "r"(dst), "l"((unsigned long long)__cvta_generic_to_global(src)) : "memory");
}
#define CP_COMMIT() asm volatile("cp.async.commit_group;" ::: "memory")
#define CP_WAIT1()  asm volatile("cp.async.wait_group 1;" ::: "memory")

// two-smallest merges with first-index tie-break (matches jnp.argmin)
__device__ __forceinline__ void upd1(float& b, float& b2, int& i, float v, int n) {
    if (v < b || (v == b && n < i)) { b2 = b; b = v; i = n; }
    else b2 = fminf(b2, v);
}
__device__ __forceinline__ void merge2(float& b, float& b2, int& i,
                                       float ob, float ob2, int oi) {
    if (ob < b || (ob == b && oi < i)) { b2 = fminf(b, ob2); b = ob; i = oi; }
    else b2 = fminf(b2, ob);
}

// ---------------- prep: row norms + zero histogram ----------------
__global__ void vq_prep_kernel(const float* __restrict__ latents,
                               const float* __restrict__ embedding) {
    const int lane = threadIdx.x & 31;
    const int warp = threadIdx.x >> 5;
    const int gw   = blockIdx.x * 8 + warp;

    const float* src = nullptr;
    float* dst = nullptr;
    int row = 0;
    if (gw < B_ROWS)                 { src = latents;   dst = g_xsq; row = gw; }
    else if (gw < B_ROWS + K_CODES)  { src = embedding; dst = g_esq; row = gw - B_ROWS; }

    if (src) {
        const float4* p = reinterpret_cast<const float4*>(src + (size_t)row * D_DIM);
        float4 a = p[lane];
        float4 b = p[lane + 32];
        float s = a.x*a.x + a.y*a.y + a.z*a.z + a.w*a.w
                + b.x*b.x + b.y*b.y + b.z*b.z + b.w*b.w;
#pragma unroll
        for (int off = 16; off; off >>= 1)
            s += __shfl_down_sync(0xffffffffu, s, off);
        if (lane == 0) dst[row] = s;
    }
    if (blockIdx.x == 0) {
        for (int k = threadIdx.x; k < K_CODES; k += blockDim.x) g_counts[k] = 0;
    }
}

// ---------------- split: fp32 -> bf16 hi/lo pairs ----------------
__global__ void vq_split_kernel(const float* __restrict__ latents,
                                const float* __restrict__ embedding) {
    int i = blockIdx.x * 256 + threadIdx.x;           // float4 index
    const int LAT4 = (B_ROWS * D_DIM) / 4;
    const float4* src;
    __nv_bfloat16 *dh, *dl;
    if (i < LAT4) { src = (const float4*)latents;  dh = g_ah; dl = g_al; }
    else { i -= LAT4; src = (const float4*)embedding; dh = g_eh; dl = g_el; }

    const float4 v = src[i];
    const float f[4] = {v.x, v.y, v.z, v.w};
    __nv_bfloat16 h[4], l[4];
#pragma unroll
    for (int t = 0; t < 4; t++) {
        h[t] = __float2bfloat16(f[t]);
        l[t] = __float2bfloat16(f[t] - __bfloat162float(h[t]));
    }
    __nv_bfloat162* ph = (__nv_bfloat162*)(dh + (size_t)i * 4);
    __nv_bfloat162* pl = (__nv_bfloat162*)(dl + (size_t)i * 4);
    ph[0] = __halves2bfloat162(h[0], h[1]);
    ph[1] = __halves2bfloat162(h[2], h[3]);
    pl[0] = __halves2bfloat162(l[0], l[1]);
    pl[1] = __halves2bfloat162(l[2], l[3]);
}

// ---------------- main: mma.sync bf16-split GEMM + fused argmin ----------------
// smem layout (bytes):
//   A: 2 splits x 128 rows x 528B (264 bf16 padded)  -> 0 .. 135168
//   B: 2 bufs x 2 splits x 128 rows x 80B            -> 135168 .. 176128
//   red: best[128]f, best2[128]f, idx[128]i          -> 176128 .. 177664
#define SM_A0    0
#define SM_A1    67584
#define SM_B     135168
#define SM_REDB  176128
#define SM_REDB2 176640
#define SM_REDI  177152
#define SMEM_TOTAL 177664

__global__ void __launch_bounds__(256, 1)
vq_main_kernel(float* __restrict__ out) {
    extern __shared__ char smem[];
    const uint32_t smb = smem_to_u32(smem);

    const int tid  = threadIdx.x;
    const int wid  = tid >> 5;
    const int lane = tid & 31;
    const int wm   = wid & 3;     // 0..3: rows wm*32..+31
    const int wn   = wid >> 2;    // 0..1: cols wn*64..+63
    const int g    = lane >> 3;
    const int r    = lane & 7;
    const int qr   = lane >> 2;   // t/4
    const int qc   = lane & 3;    // t%4
    const int row0 = blockIdx.x * 128;

    // per-lane folded ldmatrix bases
    const uint32_t aRow = (uint32_t)(wm * 32 + (g & 1) * 8 + r);
    const uint32_t aK   = (uint32_t)((g >> 1) * 16);            // bytes
    const uint32_t saBase0 = smb + SM_A0 + aRow * 528 + aK;
    const uint32_t saBase1 = smb + SM_A1 + aRow * 528 + aK;
    const uint32_t bRow = (uint32_t)((g >> 1) * 8 + r);
    const uint32_t bK   = (uint32_t)((g & 1) * 16);             // bytes
    const uint32_t sbBase = smb + SM_B + (wn * 64 + bRow) * 80 + bK;

    // ---- prologue: A tiles (both splits) via cp.async ----
#pragma unroll
    for (int sp = 0; sp < 2; sp++) {
        const __nv_bfloat16* src = sp ? g_al : g_ah;
        const uint32_t dbase = smb + (sp ? SM_A1 : SM_A0);
#pragma unroll
        for (int j = 0; j < 16; j++) {
            const int l = j * 256 + tid;
            const int row = l >> 5, seg = l & 31;
            cpa16(dbase + row * 528 + seg * 16,
                  src + (size_t)(row0 + row) * D_DIM + seg * 8);
        }
    }
    CP_COMMIT();

    // B chunk loader: step s -> jn = s>>3, kc = s&7, buf = s&1
    auto loadB = [&](int s) {
        const int jn = s >> 3, kc = s & 7, buf = s & 1;
#pragma unroll
        for (int sp = 0; sp < 2; sp++) {
            const __nv_bfloat16* src = sp ? g_el : g_eh;
            const uint32_t dbase = smb + SM_B + buf * 20480 + sp * 10240;
#pragma unroll
            for (int j = 0; j < 2; j++) {
                const int l = j * 256 + tid;
                const int row = l >> 2, seg = l & 3;
                cpa16(dbase + row * 80 + seg * 16,
                      src + (size_t)(jn * 128 + row) * D_DIM + kc * 32 + seg * 8);
            }
        }
    };
    loadB(0); CP_COMMIT();
    loadB(1); CP_COMMIT();

    // per-row xsq for my 4 row-slots (slot = mt*2 + rh)
    float xqr[4];
#pragma unroll
    for (int mt = 0; mt < 2; mt++)
#pragma unroll
        for (int rh = 0; rh < 2; rh++)
            xqr[mt * 2 + rh] = g_xsq[row0 + wm * 32 + mt * 16 + rh * 8 + qr];

    float rb[4], rb2[4];
    int   ri[4];
#pragma unroll
    for (int sl = 0; sl < 4; sl++) { rb[sl] = 3.0e38f; rb2[sl] = 3.0e38f; ri[sl] = 0; }

    for (int jn = 0; jn < 16; jn++) {
        float acc[2][8][4];
#pragma unroll
        for (int mt = 0; mt < 2; mt++)
#pragma unroll
            for (int nt = 0; nt < 8; nt++)
#pragma unroll
                for (int c = 0; c < 4; c++) acc[mt][nt][c] = 0.0f;

        for (int kc = 0; kc < 8; kc++) {
            const int s = jn * 8 + kc;
            CP_WAIT1();
            __syncthreads();
            const int buf = s & 1;

#pragma unroll
            for (int ks = 0; ks < 2; ks++) {
                uint32_t Af[2][2][4];
#pragma unroll
                for (int mt = 0; mt < 2; mt++) {
                    ldm4(Af[0][mt], saBase0 + mt * (16 * 528) + kc * 64 + ks * 32);
                    ldm4(Af[1][mt], saBase1 + mt * (16 * 528) + kc * 64 + ks * 32);
                }
#pragma unroll
                for (int spb = 0; spb < 2; spb++) {
                    uint32_t Bf[4][4];
#pragma unroll
                    for (int np = 0; np < 4; np++)
                        ldm4(Bf[np], sbBase + buf * 20480 + spb * 10240
                                     + np * (16 * 80) + ks * 32);
#pragma unroll
                    for (int mt = 0; mt < 2; mt++)
#pragma unroll
                        for (int np = 0; np < 4; np++) {
                            mma_bf16(acc[mt][np*2],   Af[0][mt], Bf[np][0], Bf[np][1]);
                            mma_bf16(acc[mt][np*2+1], Af[0][mt], Bf[np][2], Bf[np][3]);
                            if (spb == 0) {   // lh product only vs B-hi
                                mma_bf16(acc[mt][np*2],   Af[1][mt], Bf[np][0], Bf[np][1]);
                                mma_bf16(acc[mt][np*2+1], Af[1][mt], Bf[np][2], Bf[np][3]);
                            }
                        }
                }
            }
            __syncthreads();
            if (s + 2 < 128) loadB(s + 2);
            CP_COMMIT();
        }

        // epilogue: scores + running two-smallest (cols ascending per thread)
#pragma unroll
        for (int nt = 0; nt < 8; nt++) {
            const int n0 = jn * 128 + wn * 64 + nt * 8 + qc * 2;
            const float2 e2 = *(const float2*)(g_esq + n0);
#pragma unroll
            for (int mt = 0; mt < 2; mt++)
#pragma unroll
                for (int rh = 0; rh < 2; rh++) {
                    const int sl = mt * 2 + rh;
                    const float xq = xqr[sl];
                    const float v0 = (xq + e2.x) - 2.0f * acc[mt][nt][rh * 2 + 0];
                    const float v1 = (xq + e2.y) - 2.0f * acc[mt][nt][rh * 2 + 1];
                    upd1(rb[sl], rb2[sl], ri[sl], v0, n0);
                    upd1(rb[sl], rb2[sl], ri[sl], v1, n0 + 1);
                }
        }
    }

    // quad butterfly (lanes sharing a row differ in qc -> xor 1, 2)
#pragma unroll
    for (int sl = 0; sl < 4; sl++) {
#pragma unroll
        for (int m = 1; m <= 2; m <<= 1) {
            const float ob  = __shfl_xor_sync(0xffffffffu, rb[sl],  m);
            const float ob2 = __shfl_xor_sync(0xffffffffu, rb2[sl], m);
            const int   oi  = __shfl_xor_sync(0xffffffffu, ri[sl],  m);
            merge2(rb[sl], rb2[sl], ri[sl], ob, ob2, oi);
        }
    }

    // cross-warp (wn=0 vs wn=1) merge via smem
    float* red_b  = (float*)(smem + SM_REDB);
    float* red_b2 = (float*)(smem + SM_REDB2);
    int*   red_i  = (int*)(smem + SM_REDI);
    __syncthreads();
    if (wn == 0 && qc == 0) {
#pragma unroll
        for (int mt = 0; mt < 2; mt++)
#pragma unroll
            for (int rh = 0; rh < 2; rh++) {
                const int sl = mt * 2 + rh;
                const int rl = wm * 32 + mt * 16 + rh * 8 + qr;
                red_b[rl] = rb[sl]; red_b2[rl] = rb2[sl]; red_i[rl] = ri[sl];
            }
    }
    __syncthreads();
    if (wn == 1 && qc == 0) {
#pragma unroll
        for (int mt = 0; mt < 2; mt++)
#pragma unroll
            for (int rh = 0; rh < 2; rh++) {
                const int sl = mt * 2 + rh;
                const int rl = wm * 32 + mt * 16 + rh * 8 + qr;
                merge2(rb[sl], rb2[sl], ri[sl], red_b[rl], red_b2[rl], red_i[rl]);
                const int row = row0 + rl;
                g_ind[row] = ri[sl];
                out[OFF_IND + row] = (float)ri[sl];
                g_cl_val[row] = rb[sl];
                g_flag[row] = (rb2[sl] - rb[sl] < TIE_EPS) ? 1 : 0;
            }
    }
}

// ---------------- fixup: exact fp32 recompute of ambiguous rows ----------------
__global__ void vq_fixup_kernel(const float* __restrict__ latents,
                                const float* __restrict__ embedding,
                                float* __restrict__ out) {
    __shared__ float lx[256];
    __shared__ float sv[256];
    __shared__ int   si[256];
    const int tid = threadIdx.x;
    const int rbeg = blockIdx.x * 256;

    for (int rr = rbeg; rr < rbeg + 256; rr++) {
        if (!g_flag[rr]) continue;

        lx[tid] = latents[(size_t)rr * D_DIM + tid];
        __syncthreads();
        const float xq = g_xsq[rr];
        float bb = 3.0e38f;
        int bi = 0x7fffffff;
#pragma unroll
        for (int cc = 0; cc < 8; cc++) {
            const int c = cc * 256 + tid;
            const float* e = embedding + (size_t)c * D_DIM;
            float dot = 0.0f;
#pragma unroll 8
            for (int k = 0; k < D_DIM; k++) dot = fmaf(e[k], lx[k], dot);
            const float sc = (xq + g_esq[c]) - 2.0f * dot;
            if (sc < bb || (sc == bb && c < bi)) { bb = sc; bi = c; }
        }
        sv[tid] = bb; si[tid] = bi;
        __syncthreads();
        for (int o = 128; o; o >>= 1) {
            if (tid < o) {
                const float v2 = sv[tid + o]; const int i2 = si[tid + o];
                if (v2 < sv[tid] || (v2 == sv[tid] && i2 < si[tid])) { sv[tid] = v2; si[tid] = i2; }
            }
            __syncthreads();
        }
        if (tid == 0) {
            g_ind[rr] = si[0];
            out[OFF_IND + rr] = (float)si[0];
            g_cl_val[rr] = sv[0];
        }
        __syncthreads();
    }
}

// ---------------- gather + straight-through + mse partials + histogram ----------------
__global__ void vq_gather_kernel(const float* __restrict__ latents,
                                 const float* __restrict__ embedding,
                                 float* __restrict__ out) {
    const int i4 = blockIdx.x * blockDim.x + threadIdx.x;   // float4 index
    const int b  = i4 >> 6;
    const int d  = (i4 & 63) << 2;
    const int ind = g_ind[b];

    if ((i4 & 63) == 0) atomicAdd(&g_counts[ind], 1);

    const float4 q = *reinterpret_cast<const float4*>(embedding + (size_t)ind * D_DIM + d);
    const float4 x = *reinterpret_cast<const float4*>(latents + (size_t)b * D_DIM + d);

    const float dx = q.x - x.x, dy = q.y - x.y, dz = q.z - x.z, dw = q.w - x.w;
    float4 o;
    o.x = x.x + dx; o.y = x.y + dy; o.z = x.z + dz; o.w = x.w + dw;
    *reinterpret_cast<float4*>(out + (size_t)i4 * 4) = o;

    float ss = dx*dx + dy*dy + dz*dz + dw*dw;
#pragma unroll
    for (int off = 16; off; off >>= 1)
        ss += __shfl_down_sync(0xffffffffu, ss, off);

    __shared__ float w[8];
    const int lane = threadIdx.x & 31;
    const int warp = threadIdx.x >> 5;
    if (lane == 0) w[warp] = ss;
    __syncthreads();
    if (threadIdx.x == 0) {
        float t = 0.0f;
        for (int i = 0; i < 8; i++) t += w[i];
        g_mse_part[blockIdx.x] = t;
    }
}

// ---------------- finalize scalars ----------------
__global__ void vq_finalize_kernel(float* __restrict__ out) {
    __shared__ float sh[256];
    const int tid = threadIdx.x;

    float s = 0.0f;
    for (int i = tid; i < 8192; i += 256) s += g_mse_part[i];
    sh[tid] = s; __syncthreads();
    for (int o = 128; o; o >>= 1) { if (tid < o) sh[tid] += sh[tid + o]; __syncthreads(); }
    const float mse_sum = sh[0];
    __syncthreads();

    s = 0.0f;
    for (int i = tid; i < B_ROWS; i += 256) s += g_cl_val[i];
    sh[tid] = s; __syncthreads();
    for (int o = 128; o; o >>= 1) { if (tid < o) sh[tid] += sh[tid + o]; __syncthreads(); }
    const float cl_sum = sh[0];
    __syncthreads();

    s = 0.0f;
    for (int k = tid; k < K_CODES; k += 256) {
        const float p = (float)g_counts[k] * (1.0f / 32768.0f);
        s += p * logf(p + 1e-10f);
    }
    sh[tid] = s; __syncthreads();
    for (int o = 128; o; o >>= 1) { if (tid < o) sh[tid] += sh[tid + o]; __syncthreads(); }

    if (tid == 0) {
        const float m = mse_sum / 8388608.0f;
        out[OFF_VQ]  = m * 0.25f + m;
        out[OFF_ENT] = -sh[0];
        out[OFF_CL]  = cl_sum / 32768.0f;
    }
}

extern "C" void kernel_launch(void* const* d_in, const int* in_sizes, int n_in,
                              void* d_out, int out_size) {
    const float* latents   = (const float*)d_in[0];
    const float* embedding = (const float*)d_in[1];
    float* out = (float*)d_out;

    cudaFuncSetAttribute(vq_main_kernel,
                         cudaFuncAttributeMaxDynamicSharedMemorySize, SMEM_TOTAL);

    vq_prep_kernel<<<(B_ROWS + K_CODES) / 8, 256>>>(latents, embedding);
    vq_split_kernel<<<(B_ROWS * D_DIM / 4 + K_CODES * D_DIM / 4) / 256, 256>>>(latents, embedding);
    vq_main_kernel<<<B_ROWS / 128, 256, SMEM_TOTAL>>>(out);
    vq_fixup_kernel<<<B_ROWS / 256, 256>>>(latents, embedding, out);
    vq_gather_kernel<<<(B_ROWS * D_DIM) / (256 * 4), 256>>>(latents, embedding, out);
    vq_finalize_kernel<<<1, 256>>>(out);
}